// round 4
// baseline (speedup 1.0000x reference)
#include <cuda_runtime.h>
#include <cuda_bf16.h>
#include <cub/cub.cuh>
#include <cstdint>

// Problem constants (fixed shapes for this problem instance)
constexpr int H = 76, W = 128, A = 9;
constexpr int HW = H * W;               // 9728
constexpr int N = H * W * A;            // 87552
constexpr int TOPN = 6000;
constexpr int NW = (TOPN + 63) / 64;    // 94 words per mask row
constexpr int POST = 1000;
constexpr float NMS_THR = 0.7f;

// The 9 canonical Faster-RCNN anchors (base 16, ratios .5/1/2, scales 8/16/32),
// recomputed exactly per generate_anchors():
//   ratio 0.5: ws=23, hs=12 ; ratio 1: 16,16 ; ratio 2: ws=11, hs=22
//   (hs uses the ROUNDED ws: hs = round(ws*ratio))
__constant__ float c_anc[36] = {
    -84.f,  -40.f,  99.f,  55.f,
   -176.f,  -88.f, 191.f, 103.f,
   -360.f, -184.f, 375.f, 199.f,
    -56.f,  -56.f,  71.f,  71.f,
   -120.f, -120.f, 135.f, 135.f,
   -248.f, -248.f, 263.f, 263.f,
    -36.f,  -80.f,  51.f,  95.f,
    -80.f, -168.f,  95.f, 183.f,
   -168.f, -344.f, 183.f, 359.f    // y2 = 7.5 + 0.5*(22*32-1) = 359
};

// Static device scratch (no allocations allowed)
__device__ float g_sc[N];
__device__ float g_sc_o[N];
__device__ int   g_id[N];
__device__ int   g_id_o[N];
__device__ unsigned char g_cub_tmp[1 << 24];   // 16 MB for CUB radix sort
__device__ float g_x1[TOPN], g_y1[TOPN], g_x2[TOPN], g_y2[TOPN], g_ar[TOPN];
__device__ unsigned long long g_mask[TOPN * NW];

// ---------------------------------------------------------------------------
// K1: extract foreground scores (channels A..2A-1) into (H,W,A)-flattened
// order, plus iota indices for the stable sort. Thread order follows the
// INPUT layout (channel-major) so global loads are fully coalesced.
// ---------------------------------------------------------------------------
__global__ void score_kernel(const float* __restrict__ scores)
{
    int g = blockIdx.x * blockDim.x + threadIdx.x;   // g = a*HW + hw
    if (g >= N) return;
    int a  = g / HW;
    int hw = g - a * HW;
    int idx = hw * A + a;                            // (h,w,a)-major position
    g_sc[idx] = scores[(A + a) * HW + hw];
    g_id[idx] = idx;
}

// ---------------------------------------------------------------------------
// K2: decode + clip boxes for the top-6000 only. Explicit round-to-nearest
// intrinsics prevent FMA contraction (match XLA per-op rounding).
// ---------------------------------------------------------------------------
__global__ void decode_kernel(const float* __restrict__ deltas,
                              const float* __restrict__ im_info)
{
    int j = blockIdx.x * blockDim.x + threadIdx.x;
    if (j >= TOPN) return;
    int idx = g_id_o[j];
    int a   = idx % A;
    int hw  = idx / A;
    int w   = hw % W;
    int h   = hw / W;

    float ax1 = c_anc[a * 4 + 0] + 16.f * (float)w;
    float ay1 = c_anc[a * 4 + 1] + 16.f * (float)h;
    float ax2 = c_anc[a * 4 + 2] + 16.f * (float)w;
    float ay2 = c_anc[a * 4 + 3] + 16.f * (float)h;

    float aw  = __fadd_rn(__fsub_rn(ax2, ax1), 1.0f);
    float ah  = __fadd_rn(__fsub_rn(ay2, ay1), 1.0f);
    float acx = __fadd_rn(ax1, __fmul_rn(0.5f, aw));
    float acy = __fadd_rn(ay1, __fmul_rn(0.5f, ah));

    int base = h * W + w;
    float d0 = deltas[(4 * a + 0) * HW + base];
    float d1 = deltas[(4 * a + 1) * HW + base];
    float d2 = deltas[(4 * a + 2) * HW + base];
    float d3 = deltas[(4 * a + 3) * HW + base];

    float pcx = __fadd_rn(__fmul_rn(d0, aw), acx);
    float pcy = __fadd_rn(__fmul_rn(d1, ah), acy);
    float pw  = __fmul_rn(expf(d2), aw);
    float ph  = __fmul_rn(expf(d3), ah);

    float bx1 = __fsub_rn(pcx, __fmul_rn(0.5f, pw));
    float by1 = __fsub_rn(pcy, __fmul_rn(0.5f, ph));
    float bx2 = __fadd_rn(pcx, __fmul_rn(0.5f, pw));
    float by2 = __fadd_rn(pcy, __fmul_rn(0.5f, ph));

    float xmax = __fsub_rn(im_info[1], 1.0f);
    float ymax = __fsub_rn(im_info[0], 1.0f);
    bx1 = fminf(fmaxf(bx1, 0.0f), xmax);
    by1 = fminf(fmaxf(by1, 0.0f), ymax);
    bx2 = fminf(fmaxf(bx2, 0.0f), xmax);
    by2 = fminf(fmaxf(by2, 0.0f), ymax);

    g_x1[j] = bx1; g_y1[j] = by1; g_x2[j] = bx2; g_y2[j] = by2;
    g_ar[j] = __fmul_rn(__fadd_rn(__fsub_rn(bx2, bx1), 1.0f),
                        __fadd_rn(__fsub_rn(by2, by1), 1.0f));
}

// ---------------------------------------------------------------------------
// K3: NMS suppression bitmask. Block (rb, cb) handles 64 rows x 64 cols.
// Only the upper triangle (cb >= rb) is computed; only bits j > i are set.
// ---------------------------------------------------------------------------
__global__ __launch_bounds__(64) void nms_mask_kernel()
{
    int rb = blockIdx.y, cb = blockIdx.x;
    if (cb < rb) return;

    __shared__ float sx1[64], sy1[64], sx2[64], sy2[64], sar[64];
    int t  = threadIdx.x;
    int j0 = cb * 64;
    int jn = min(64, TOPN - j0);
    if (t < jn) {
        sx1[t] = g_x1[j0 + t]; sy1[t] = g_y1[j0 + t];
        sx2[t] = g_x2[j0 + t]; sy2[t] = g_y2[j0 + t];
        sar[t] = g_ar[j0 + t];
    }
    __syncthreads();

    int i = rb * 64 + t;
    if (i >= TOPN) return;

    float x1 = g_x1[i], y1 = g_y1[i], x2 = g_x2[i], y2 = g_y2[i], ar = g_ar[i];
    unsigned long long bits = 0;
    int start = (rb == cb) ? t + 1 : 0;
    #pragma unroll 4
    for (int k = start; k < jn; ++k) {
        float iw = __fadd_rn(__fsub_rn(fminf(x2, sx2[k]), fmaxf(x1, sx1[k])), 1.0f);
        float ih = __fadd_rn(__fsub_rn(fminf(y2, sy2[k]), fmaxf(y1, sy1[k])), 1.0f);
        iw = fmaxf(iw, 0.0f);
        ih = fmaxf(ih, 0.0f);
        float inter = __fmul_rn(iw, ih);
        float denom = __fsub_rn(__fadd_rn(ar, sar[k]), inter);
        float iou   = __fdiv_rn(inter, denom);
        if (iou > NMS_THR) bits |= (1ull << k);
    }
    g_mask[(size_t)i * NW + cb] = bits;
}

// ---------------------------------------------------------------------------
// K4: sequential NMS reduce (chunked), selection, and output gather.
// Single block, 128 threads. keepw[c] records kept bits per 64-row chunk.
// ---------------------------------------------------------------------------
__global__ __launch_bounds__(128) void nms_scan_kernel(float* __restrict__ out)
{
    __shared__ unsigned long long remv[NW];
    __shared__ unsigned long long keepw[NW];
    __shared__ unsigned long long buf[64];
    __shared__ int sel[POST];

    int tid = threadIdx.x;
    for (int w = tid; w < NW; w += blockDim.x) remv[w] = 0ull;
    __syncthreads();

    for (int c = 0; c < NW; ++c) {
        // cooperative prefetch of this chunk's diagonal mask column
        if (tid < 64) {
            int i = c * 64 + tid;
            buf[tid] = (i < TOPN) ? g_mask[(size_t)i * NW + c] : 0ull;
        }
        __syncthreads();

        // phase A: one thread resolves the intra-chunk serial dependency
        if (tid == 0) {
            unsigned long long rm = remv[c];
            unsigned long long kb = 0ull;
            int lim = min(64, TOPN - c * 64);
            for (int k = 0; k < lim; ++k) {
                if (!((rm >> k) & 1ull)) {
                    kb |= (1ull << k);
                    rm |= buf[k];
                }
            }
            keepw[c] = kb;
            remv[c]  = rm;
        }
        __syncthreads();

        // phase B: propagate kept rows' suppression into later words
        unsigned long long kb = keepw[c];
        if (kb) {
            for (int w = c + 1 + tid; w < NW; w += blockDim.x) {
                unsigned long long acc = remv[w];
                unsigned long long tmp = kb;
                while (tmp) {
                    int k = __ffsll((long long)tmp) - 1;
                    tmp &= tmp - 1;
                    acc |= g_mask[(size_t)(c * 64 + k) * NW + w];
                }
                remv[w] = acc;
            }
        }
        __syncthreads();
    }

    // selection: kept indices in order, then suppressed (== masked top_k of
    // (score, -inf) with stable ties), truncated to POST
    if (tid == 0) {
        int cnt = 0;
        for (int j = 0; j < TOPN && cnt < POST; ++j)
            if ((keepw[j >> 6] >> (j & 63)) & 1ull) sel[cnt++] = j;
        for (int j = 0; j < TOPN && cnt < POST; ++j)
            if (!((keepw[j >> 6] >> (j & 63)) & 1ull)) sel[cnt++] = j;
    }
    __syncthreads();

    for (int s = tid; s < POST; s += blockDim.x) {
        int j = sel[s];
        out[4 * s + 0] = g_x1[j];
        out[4 * s + 1] = g_y1[j];
        out[4 * s + 2] = g_x2[j];
        out[4 * s + 3] = g_y2[j];
    }
}

// ---------------------------------------------------------------------------
extern "C" void kernel_launch(void* const* d_in, const int* in_sizes, int n_in,
                              void* d_out, int out_size)
{
    const float* scores  = (const float*)d_in[0];
    const float* deltas  = (const float*)d_in[1];
    const float* im_info = (const float*)d_in[2];
    float* out = (float*)d_out;

    score_kernel<<<(N + 255) / 256, 256>>>(scores);

    void *ks, *ko, *vs, *vo, *tmp;
    cudaGetSymbolAddress(&ks,  g_sc);
    cudaGetSymbolAddress(&ko,  g_sc_o);
    cudaGetSymbolAddress(&vs,  g_id);
    cudaGetSymbolAddress(&vo,  g_id_o);
    cudaGetSymbolAddress(&tmp, g_cub_tmp);

    size_t bytes = 0;
    cub::DeviceRadixSort::SortPairsDescending(
        nullptr, bytes, (const float*)ks, (float*)ko,
        (const int*)vs, (int*)vo, N);
    if (bytes <= (size_t)(1 << 24)) {
        cub::DeviceRadixSort::SortPairsDescending(
            tmp, bytes, (const float*)ks, (float*)ko,
            (const int*)vs, (int*)vo, N);
    }

    decode_kernel<<<(TOPN + 127) / 128, 128>>>(deltas, im_info);

    dim3 grid(NW, NW);
    nms_mask_kernel<<<grid, 64>>>();

    nms_scan_kernel<<<1, 128>>>(out);
}

// round 5
// speedup vs baseline: 2.5307x; 2.5307x over previous
#include <cuda_runtime.h>
#include <cuda_bf16.h>
#include <cub/cub.cuh>
#include <cstdint>

// Problem constants (fixed shapes for this problem instance)
constexpr int H = 76, W = 128, A = 9;
constexpr int HW = H * W;               // 9728
constexpr int N = H * W * A;            // 87552
constexpr int TOPN = 6000;
constexpr int NW = (TOPN + 63) / 64;    // 94 words per mask row
constexpr int POST = 1000;
constexpr float NMS_THR = 0.7f;

// The 9 canonical Faster-RCNN anchors (base 16, ratios .5/1/2, scales 8/16/32)
__constant__ float c_anc[36] = {
    -84.f,  -40.f,  99.f,  55.f,
   -176.f,  -88.f, 191.f, 103.f,
   -360.f, -184.f, 375.f, 199.f,
    -56.f,  -56.f,  71.f,  71.f,
   -120.f, -120.f, 135.f, 135.f,
   -248.f, -248.f, 263.f, 263.f,
    -36.f,  -80.f,  51.f,  95.f,
    -80.f, -168.f,  95.f, 183.f,
   -168.f, -344.f, 183.f, 359.f
};

// Static device scratch (no allocations allowed)
__device__ float g_sc[N];
__device__ float g_sc_o[N];
__device__ int   g_id[N];
__device__ int   g_id_o[N];
__device__ unsigned char g_cub_tmp[1 << 24];   // 16 MB for CUB radix sort
__device__ float g_x1[TOPN], g_y1[TOPN], g_x2[TOPN], g_y2[TOPN], g_ar[TOPN];
__device__ unsigned long long g_mask[TOPN * NW];

// ---------------------------------------------------------------------------
// K1: extract foreground scores, coalesced on the input layout.
// ---------------------------------------------------------------------------
__global__ void score_kernel(const float* __restrict__ scores)
{
    int g = blockIdx.x * blockDim.x + threadIdx.x;   // g = a*HW + hw
    if (g >= N) return;
    int a  = g / HW;
    int hw = g - a * HW;
    int idx = hw * A + a;                            // (h,w,a)-major position
    g_sc[idx] = scores[(A + a) * HW + hw];
    g_id[idx] = idx;
}

// ---------------------------------------------------------------------------
// K2: decode + clip boxes for the top-6000 only (strict rn rounding).
// ---------------------------------------------------------------------------
__global__ void decode_kernel(const float* __restrict__ deltas,
                              const float* __restrict__ im_info)
{
    int j = blockIdx.x * blockDim.x + threadIdx.x;
    if (j >= TOPN) return;
    int idx = g_id_o[j];
    int a   = idx % A;
    int hw  = idx / A;
    int w   = hw % W;
    int h   = hw / W;

    float ax1 = c_anc[a * 4 + 0] + 16.f * (float)w;
    float ay1 = c_anc[a * 4 + 1] + 16.f * (float)h;
    float ax2 = c_anc[a * 4 + 2] + 16.f * (float)w;
    float ay2 = c_anc[a * 4 + 3] + 16.f * (float)h;

    float aw  = __fadd_rn(__fsub_rn(ax2, ax1), 1.0f);
    float ah  = __fadd_rn(__fsub_rn(ay2, ay1), 1.0f);
    float acx = __fadd_rn(ax1, __fmul_rn(0.5f, aw));
    float acy = __fadd_rn(ay1, __fmul_rn(0.5f, ah));

    int base = h * W + w;
    float d0 = deltas[(4 * a + 0) * HW + base];
    float d1 = deltas[(4 * a + 1) * HW + base];
    float d2 = deltas[(4 * a + 2) * HW + base];
    float d3 = deltas[(4 * a + 3) * HW + base];

    float pcx = __fadd_rn(__fmul_rn(d0, aw), acx);
    float pcy = __fadd_rn(__fmul_rn(d1, ah), acy);
    float pw  = __fmul_rn(expf(d2), aw);
    float ph  = __fmul_rn(expf(d3), ah);

    float bx1 = __fsub_rn(pcx, __fmul_rn(0.5f, pw));
    float by1 = __fsub_rn(pcy, __fmul_rn(0.5f, ph));
    float bx2 = __fadd_rn(pcx, __fmul_rn(0.5f, pw));
    float by2 = __fadd_rn(pcy, __fmul_rn(0.5f, ph));

    float xmax = __fsub_rn(im_info[1], 1.0f);
    float ymax = __fsub_rn(im_info[0], 1.0f);
    bx1 = fminf(fmaxf(bx1, 0.0f), xmax);
    by1 = fminf(fmaxf(by1, 0.0f), ymax);
    bx2 = fminf(fmaxf(bx2, 0.0f), xmax);
    by2 = fminf(fmaxf(by2, 0.0f), ymax);

    g_x1[j] = bx1; g_y1[j] = by1; g_x2[j] = bx2; g_y2[j] = by2;
    g_ar[j] = __fmul_rn(__fadd_rn(__fsub_rn(bx2, bx1), 1.0f),
                        __fadd_rn(__fsub_rn(by2, by1), 1.0f));
}

// ---------------------------------------------------------------------------
// K3: NMS suppression bitmask (upper triangle).
// ---------------------------------------------------------------------------
__global__ __launch_bounds__(64) void nms_mask_kernel()
{
    int rb = blockIdx.y, cb = blockIdx.x;
    if (cb < rb) return;

    __shared__ float sx1[64], sy1[64], sx2[64], sy2[64], sar[64];
    int t  = threadIdx.x;
    int j0 = cb * 64;
    int jn = min(64, TOPN - j0);
    if (t < jn) {
        sx1[t] = g_x1[j0 + t]; sy1[t] = g_y1[j0 + t];
        sx2[t] = g_x2[j0 + t]; sy2[t] = g_y2[j0 + t];
        sar[t] = g_ar[j0 + t];
    }
    __syncthreads();

    int i = rb * 64 + t;
    if (i >= TOPN) return;

    float x1 = g_x1[i], y1 = g_y1[i], x2 = g_x2[i], y2 = g_y2[i], ar = g_ar[i];
    unsigned long long bits = 0;
    int start = (rb == cb) ? t + 1 : 0;
    #pragma unroll 4
    for (int k = start; k < jn; ++k) {
        float iw = __fadd_rn(__fsub_rn(fminf(x2, sx2[k]), fmaxf(x1, sx1[k])), 1.0f);
        float ih = __fadd_rn(__fsub_rn(fminf(y2, sy2[k]), fmaxf(y1, sy1[k])), 1.0f);
        iw = fmaxf(iw, 0.0f);
        ih = fmaxf(ih, 0.0f);
        float inter = __fmul_rn(iw, ih);
        float denom = __fsub_rn(__fadd_rn(ar, sar[k]), inter);
        float iou   = __fdiv_rn(inter, denom);
        if (iou > NMS_THR) bits |= (1ull << k);
    }
    g_mask[(size_t)i * NW + cb] = bits;
}

// ---------------------------------------------------------------------------
// K4: NMS reduce, REWRITTEN.
//  - 1024 threads: each later mask word has ONE owner thread in phase B, so
//    each thread's bit-loop issues independent LDGs (pipelined, not serial).
//  - phase A: warp 0 holds the 64 diagonal words in lanes; the greedy keep
//    chain runs via ffsll + shfl broadcast instead of a thread-0 LDS chain.
//  - early exit once cumulative kept >= POST (later chunks can't affect out).
// ---------------------------------------------------------------------------
__global__ __launch_bounds__(1024) void nms_scan_kernel(float* __restrict__ out)
{
    __shared__ unsigned long long remv[NW];
    __shared__ unsigned long long keepw[NW];
    __shared__ int s_kept;
    __shared__ int sel[POST];

    int tid = threadIdx.x;
    if (tid < NW) remv[tid] = 0ull;
    if (tid == 0) s_kept = 0;
    __syncthreads();

    int nchunks = NW;
    for (int c = 0; c < NW; ++c) {
        // ---- phase A: warp 0 resolves the intra-chunk greedy chain ----
        if (tid < 32) {
            int row0 = c * 64 + tid;
            int row1 = row0 + 32;
            unsigned long long m0 = (row0 < TOPN) ? g_mask[(size_t)row0 * NW + c] : 0ull;
            unsigned long long m1 = (row1 < TOPN) ? g_mask[(size_t)row1 * NW + c] : 0ull;
            unsigned long long rm = remv[c];
            int lim = min(64, TOPN - c * 64);
            unsigned long long valid = (lim >= 64) ? ~0ull : ((1ull << lim) - 1ull);
            unsigned long long kb = 0ull;
            unsigned long long cand;
            while ((cand = valid & ~rm) != 0ull) {
                int k = __ffsll((long long)cand) - 1;
                valid &= ~(1ull << k);
                kb |= (1ull << k);
                unsigned long long pick = (k < 32) ? m0 : m1;
                unsigned long long v = __shfl_sync(0xffffffffu, pick, k & 31);
                rm |= v;
            }
            if (tid == 0) {
                keepw[c] = kb;
                s_kept += __popcll(kb);
            }
        }
        __syncthreads();

        unsigned long long kb = keepw[c];
        bool done = (s_kept >= POST);

        // ---- phase B: one thread per later word, pipelined bit-loop ----
        if (!done && kb) {
            int w = c + 1 + tid;
            if (w < NW) {
                unsigned long long acc = remv[w];
                unsigned long long tmp = kb;
                int base = c * 64;
                while (tmp) {
                    int k = __ffsll((long long)tmp) - 1;
                    tmp &= tmp - 1;
                    acc |= g_mask[(size_t)(base + k) * NW + w];
                }
                remv[w] = acc;
            }
        }
        __syncthreads();
        if (done) { nchunks = c + 1; break; }
    }

    // selection: kept indices in order, then suppressed, truncated to POST.
    // (If we early-exited, kept alone already covers POST.)
    if (tid == 0) {
        int cnt = 0;
        int jmax = min(TOPN, nchunks * 64);
        for (int j = 0; j < jmax && cnt < POST; ++j)
            if ((keepw[j >> 6] >> (j & 63)) & 1ull) sel[cnt++] = j;
        for (int j = 0; j < TOPN && cnt < POST; ++j)
            if (!((keepw[j >> 6] >> (j & 63)) & 1ull)) sel[cnt++] = j;
    }
    __syncthreads();

    for (int s = tid; s < POST; s += blockDim.x) {
        int j = sel[s];
        out[4 * s + 0] = g_x1[j];
        out[4 * s + 1] = g_y1[j];
        out[4 * s + 2] = g_x2[j];
        out[4 * s + 3] = g_y2[j];
    }
}

// ---------------------------------------------------------------------------
extern "C" void kernel_launch(void* const* d_in, const int* in_sizes, int n_in,
                              void* d_out, int out_size)
{
    const float* scores  = (const float*)d_in[0];
    const float* deltas  = (const float*)d_in[1];
    const float* im_info = (const float*)d_in[2];
    float* out = (float*)d_out;

    score_kernel<<<(N + 255) / 256, 256>>>(scores);

    void *ks, *ko, *vs, *vo, *tmp;
    cudaGetSymbolAddress(&ks,  g_sc);
    cudaGetSymbolAddress(&ko,  g_sc_o);
    cudaGetSymbolAddress(&vs,  g_id);
    cudaGetSymbolAddress(&vo,  g_id_o);
    cudaGetSymbolAddress(&tmp, g_cub_tmp);

    size_t bytes = 0;
    cub::DeviceRadixSort::SortPairsDescending(
        nullptr, bytes, (const float*)ks, (float*)ko,
        (const int*)vs, (int*)vo, N);
    if (bytes <= (size_t)(1 << 24)) {
        cub::DeviceRadixSort::SortPairsDescending(
            tmp, bytes, (const float*)ks, (float*)ko,
            (const int*)vs, (int*)vo, N);
    }

    decode_kernel<<<(TOPN + 127) / 128, 128>>>(deltas, im_info);

    dim3 grid(NW, NW);
    nms_mask_kernel<<<grid, 64>>>();

    nms_scan_kernel<<<1, 1024>>>(out);
}